// round 12
// baseline (speedup 1.0000x reference)
#include <cuda_runtime.h>
#include <math.h>

#define BN 512
#define TD 2048
#define SD 768
#define HD 128

typedef unsigned long long ull;

// Scratch (device globals — no allocations allowed)
__device__ float g_tpp[32 * BN * HD];   // teacher proj partials (KLEN=64)
__device__ float g_spp[12 * BN * HD];   // student proj partials
// Transposed U/V: [h][row]
__device__ float g_UtT[HD * BN];
__device__ float g_VtT[HD * BN];
__device__ float g_UsT[HD * BN];
__device__ float g_VsT[HD * BN];

// ---- packed f32x2 helpers (sm_100+) --------------------------------------
__device__ __forceinline__ ull pk2(float a, float b) {
    ull r; asm("mov.b64 %0, {%1, %2};" : "=l"(r) : "f"(a), "f"(b)); return r;
}
__device__ __forceinline__ float2 unpk2(ull v) {
    float2 r; asm("mov.b64 {%0, %1}, %2;" : "=f"(r.x), "=f"(r.y) : "l"(v)); return r;
}
__device__ __forceinline__ void fma2(ull &acc, ull a, ull b) {
    asm("fma.rn.f32x2 %0, %1, %2, %0;" : "+l"(acc) : "l"(a), "l"(b));
}
// acc += relu(u + v) * w, fully packed.
// relu(x)*w = (x + |x|) * (w/2); wh pre-halved. Exact vs fl(relu(x)*w).
__device__ __forceinline__ void rabs(ull &acc, ull u, ull v, ull wh) {
    asm("{\n\t"
        ".reg .b64 t, ta;\n\t"
        "add.rn.f32x2 t, %1, %2;\n\t"
        "and.b64 ta, t, 0x7FFFFFFF7FFFFFFF;\n\t"
        "add.rn.f32x2 t, t, ta;\n\t"
        "fma.rn.f32x2 %0, t, %3, %0;\n\t"
        "}"
        : "+l"(acc) : "l"(u), "l"(v), "l"(wh));
}

// ---------------------------------------------------------------------------
// Projection GEMM partials, single-stage. z=0 teacher (32 splits), z=1
// student (12). KLEN=64. Block: 32 rows x 128 cols, 128 thr, micro 4r x 8c.
// Entire X (32r x 64k) and W (64k x 128c) tiles staged ONCE, one barrier,
// then a 64-deep barrier-free inner loop. Zeroes the output scalar.
// ---------------------------------------------------------------------------
__global__ void __launch_bounds__(128)
proj_gemm(const float* __restrict__ T, const float* __restrict__ Wt,
          const float* __restrict__ S, const float* __restrict__ Ws,
          float* __restrict__ out, int out_size) {
    const int KL = 64;
    const int XP = 36;
    __shared__ __align__(16) float Xst[KL * XP];      // [k][r] transposed, 9.2KB
    __shared__ __align__(16) float Wsm[KL * HD];      // [kk][c], 32KB

    if (blockIdx.x == 0 && blockIdx.y == 0 && blockIdx.z == 0 && threadIdx.x == 0)
        for (int i = 0; i < out_size; i++) out[i] = 0.0f;

    int z = blockIdx.z;
    int ky = blockIdx.y;
    const float* X; const float* W; float* outp; int ldx;
    if (z == 0) { X = T; W = Wt; ldx = TD; outp = g_tpp + ky * (BN * HD); }
    else {
        if (ky >= 12) return;
        X = S; W = Ws; ldx = SD; outp = g_spp + ky * (BN * HD);
    }

    int tid = threadIdx.x;        // 128
    int tx = tid & 15;            // cols tx*8..+7
    int ty = tid >> 4;            // rows ty*4..+3
    int row0 = blockIdx.x * 32;
    int k0 = ky * KL;

    // ---- Stage X: 32r x 64k (512 float4, 4/thread), transposed ----
#pragma unroll
    for (int t = 0; t < 4; t++) {
        int i4 = tid + t * 128;
        int r = i4 >> 4, k4 = (i4 & 15) * 4;
        float4 v = *reinterpret_cast<const float4*>(
            &X[(row0 + r) * ldx + k0 + k4]);
        Xst[(k4 + 0) * XP + r] = v.x;
        Xst[(k4 + 1) * XP + r] = v.y;
        Xst[(k4 + 2) * XP + r] = v.z;
        Xst[(k4 + 3) * XP + r] = v.w;
    }
    // ---- Stage W: 64k x 128c (2048 float4, 16/thread) ----
#pragma unroll
    for (int t = 0; t < 16; t++) {
        int i4 = tid + t * 128;
        int kk = i4 >> 5, c4 = (i4 & 31) * 4;
        *reinterpret_cast<float4*>(&Wsm[kk * HD + c4]) =
            *reinterpret_cast<const float4*>(&W[(k0 + kk) * HD + c4]);
    }
    __syncthreads();

    ull acc[4][4];                // [colpair q][row m]
#pragma unroll
    for (int q = 0; q < 4; q++)
#pragma unroll
        for (int m = 0; m < 4; m++) acc[q][m] = 0ull;

#pragma unroll 8
    for (int kk = 0; kk < KL; kk++) {
        float4 a4 = *reinterpret_cast<const float4*>(&Xst[kk * XP + ty * 4]);
        ulonglong2 b01 = *reinterpret_cast<const ulonglong2*>(&Wsm[kk * HD + tx * 8]);
        ulonglong2 b23 = *reinterpret_cast<const ulonglong2*>(&Wsm[kk * HD + tx * 8 + 4]);
        ull a0 = pk2(a4.x, a4.x), a1 = pk2(a4.y, a4.y);
        ull a2 = pk2(a4.z, a4.z), a3 = pk2(a4.w, a4.w);
        fma2(acc[0][0], a0, b01.x); fma2(acc[0][1], a1, b01.x);
        fma2(acc[0][2], a2, b01.x); fma2(acc[0][3], a3, b01.x);
        fma2(acc[1][0], a0, b01.y); fma2(acc[1][1], a1, b01.y);
        fma2(acc[1][2], a2, b01.y); fma2(acc[1][3], a3, b01.y);
        fma2(acc[2][0], a0, b23.x); fma2(acc[2][1], a1, b23.x);
        fma2(acc[2][2], a2, b23.x); fma2(acc[2][3], a3, b23.x);
        fma2(acc[3][0], a0, b23.y); fma2(acc[3][1], a1, b23.y);
        fma2(acc[3][2], a2, b23.y); fma2(acc[3][3], a3, b23.y);
    }

#pragma unroll
    for (int m = 0; m < 4; m++) {
        int row = row0 + ty * 4 + m;
        float2 q0 = unpk2(acc[0][m]);
        float2 q1 = unpk2(acc[1][m]);
        float2 q2 = unpk2(acc[2][m]);
        float2 q3 = unpk2(acc[3][m]);
        *reinterpret_cast<float4*>(&outp[row * HD + tx * 8]) =
            make_float4(q0.x, q0.y, q1.x, q1.y);
        *reinterpret_cast<float4*>(&outp[row * HD + tx * 8 + 4]) =
            make_float4(q2.x, q2.y, q3.x, q3.y);
    }
}

// ---------------------------------------------------------------------------
// Fused sum-partials + U/V projection, BOTH W1 halves per block (partials
// read once). grid (32 rowblocks of 16, 2 nets) = 64 blocks, 256 thr
// (two 128-thr subs, one per W1 half). Outputs TRANSPOSED [h][row].
// ---------------------------------------------------------------------------
__global__ void __launch_bounds__(256)
fused_sumuv(const float* __restrict__ bt, const float* __restrict__ bs,
            const float* __restrict__ W1, const float* __restrict__ b1) {
    const int XS = 18;
    const int WS = 132;
    __shared__ float Xst[HD * XS];                    // [k][r], 16 rows, 9.2KB
    __shared__ __align__(16) float Wsm[2][32 * WS];   // per-sub W chunk, 33.8KB

    int rb = blockIdx.x;
    int net = blockIdx.y;
    const float* pbase = net ? g_spp : g_tpp;
    const float* bias = net ? bs : bt;
    int np = net ? 12 : 32;

    int tid = threadIdx.x;        // 256
    int sub = tid >> 7;           // W1 half: 0 = U (add b1), 1 = V
    int tt = tid & 127;
    int r0 = rb * 16;

    // ---- Phase A (all 256 threads): X = bias + sum partials, transposed ----
    {
        int r[2], c4[2];
        float4 acc[2];
#pragma unroll
        for (int t = 0; t < 2; t++) {
            int i4 = tid + t * 256;
            r[t] = i4 >> 5;
            c4[t] = (i4 & 31) * 4;
            acc[t] = *reinterpret_cast<const float4*>(&bias[c4[t]]);
        }
#pragma unroll 4
        for (int p = 0; p < np; p++) {
            const float* src = pbase + p * (BN * HD);
#pragma unroll
            for (int t = 0; t < 2; t++) {
                float4 v = *reinterpret_cast<const float4*>(
                    &src[(r0 + r[t]) * HD + c4[t]]);
                acc[t].x += v.x; acc[t].y += v.y;
                acc[t].z += v.z; acc[t].w += v.w;
            }
        }
#pragma unroll
        for (int t = 0; t < 2; t++) {
            Xst[(c4[t] + 0) * XS + r[t]] = acc[t].x;
            Xst[(c4[t] + 1) * XS + r[t]] = acc[t].y;
            Xst[(c4[t] + 2) * XS + r[t]] = acc[t].z;
            Xst[(c4[t] + 3) * XS + r[t]] = acc[t].w;
        }
    }

    // ---- Phase B: each sub GEMMs 16r x 128c with its W1 half ----
    const float* W = W1 + sub * HD * HD;
    float* outT = net ? (sub ? g_VsT : g_UsT) : (sub ? g_VtT : g_UtT);
    int tx = tt & 15;
    int ty = tt >> 4;

    ull acc[2][4];                // [row m][colpair q]
#pragma unroll
    for (int m = 0; m < 2; m++)
#pragma unroll
        for (int q = 0; q < 4; q++) acc[m][q] = 0ull;

    for (int kc = 0; kc < HD; kc += 32) {
        __syncthreads();
        // stage this sub's W chunk: 32k x 128c = 1024 f4, 8/thread
#pragma unroll
        for (int t = 0; t < 8; t++) {
            int i4 = tt + t * 128;
            int kk = i4 >> 5, c4 = (i4 & 31) * 4;
            *reinterpret_cast<float4*>(&Wsm[sub][kk * WS + c4]) =
                *reinterpret_cast<const float4*>(&W[(kc + kk) * HD + c4]);
        }
        __syncthreads();
#pragma unroll 8
        for (int kk = 0; kk < 32; kk++) {
            float a0 = Xst[(kc + kk) * XS + ty * 2];
            float a1 = Xst[(kc + kk) * XS + ty * 2 + 1];
            ulonglong2 b01 = *reinterpret_cast<const ulonglong2*>(&Wsm[sub][kk * WS + tx * 8]);
            ulonglong2 b23 = *reinterpret_cast<const ulonglong2*>(&Wsm[sub][kk * WS + tx * 8 + 4]);
            ull ad0 = pk2(a0, a0), ad1 = pk2(a1, a1);
            fma2(acc[0][0], ad0, b01.x); fma2(acc[0][1], ad0, b01.y);
            fma2(acc[0][2], ad0, b23.x); fma2(acc[0][3], ad0, b23.y);
            fma2(acc[1][0], ad1, b01.x); fma2(acc[1][1], ad1, b01.y);
            fma2(acc[1][2], ad1, b23.x); fma2(acc[1][3], ad1, b23.y);
        }
    }

    int rbase = r0 + ty * 2;
#pragma unroll
    for (int q = 0; q < 4; q++) {
        int c = tx * 8 + q * 2;
        float2 p0 = unpk2(acc[0][q]);
        float2 p1 = unpk2(acc[1][q]);
        float bA = sub ? 0.0f : b1[c];
        float bB = sub ? 0.0f : b1[c + 1];
        *reinterpret_cast<float2*>(&outT[c * BN + rbase]) =
            make_float2(p0.x + bA, p1.x + bA);
        *reinterpret_cast<float2*>(&outT[(c + 1) * BN + rbase]) =
            make_float2(p0.y + bB, p1.y + bB);
    }
}

// ---------------------------------------------------------------------------
// Fused pairwise + sigmoid + MSE, one launch, no pd buffers.
// grid (16,16) = 256 blocks, 256 thr. Block = 4 quarters of 64 threads:
// quarter (g, n) computes the 32x32 dot tile for net n over h-half g,
// micro 4i x 4j = 8 independent rabs chains. HB=16 (8 barriers total).
// Halves combined via smem, then inline sigmoid/MSE/atomicAdd.
// ---------------------------------------------------------------------------
__global__ void __launch_bounds__(256)
pairwise_mse(const float* __restrict__ w2, const float* __restrict__ b2v,
             float* __restrict__ out) {
    const int HB = 16;   // h staged per chunk per quarter
    __shared__ __align__(16) float sU[2][2][HB * 32];   // [g][n][h][i]  8KB
    __shared__ __align__(16) ull  sVd[2][2][HB * 32];   // [g][n][h][j] 16KB
    __shared__ ull swd[HD];                             // (w/2, w/2)    1KB
    __shared__ float sdot[2][2][32 * 32];               //              16KB
    __shared__ float sred[256];                         //               1KB

    int tid = threadIdx.x;
    int g = tid >> 7;            // h-half
    int n = (tid >> 6) & 1;      // net
    int tt = tid & 63;
    int tx = tt & 7;             // j = jb + tx*4 + {0..3}
    int ty = tt >> 3;            // i = ib + ty*4 + {0..3}
    int jb = blockIdx.x * 32;
    int ib = blockIdx.y * 32;
    int hb0 = g * 64;

    const float* UT = n ? g_UsT : g_UtT;
    const float* VT = n ? g_VsT : g_VtT;

    if (tid < HD) { float w = w2[tid] * 0.5f; swd[tid] = pk2(w, w); }

    ull acc[4][2];               // [j-offset][i-pair]
#pragma unroll
    for (int q = 0; q < 4; q++) { acc[q][0] = 0ull; acc[q][1] = 0ull; }

    for (int hc = 0; hc < 64; hc += HB) {
        __syncthreads();         // first iter: covers swd; later: acc-read done
#pragma unroll
        for (int t = 0; t < 2; t++) {
            int id = tt + t * 64;
            int h = id >> 3, c4s = (id & 7) * 4;
            int hg = hb0 + hc + h;
            *reinterpret_cast<float4*>(&sU[g][n][h * 32 + c4s]) =
                *reinterpret_cast<const float4*>(&UT[hg * BN + ib + c4s]);
            float4 v = *reinterpret_cast<const float4*>(&VT[hg * BN + jb + c4s]);
            ulonglong2 p0, p1;
            p0.x = pk2(v.x, v.x); p0.y = pk2(v.y, v.y);
            p1.x = pk2(v.z, v.z); p1.y = pk2(v.w, v.w);
            *reinterpret_cast<ulonglong2*>(&sVd[g][n][h * 32 + c4s]) = p0;
            *reinterpret_cast<ulonglong2*>(&sVd[g][n][h * 32 + c4s + 2]) = p1;
        }
        __syncthreads();
#pragma unroll
        for (int hh = 0; hh < HB; hh++) {
            ulonglong2 u2 = *reinterpret_cast<const ulonglong2*>(
                &sU[g][n][hh * 32 + ty * 4]);
            ulonglong2 vd0 = *reinterpret_cast<const ulonglong2*>(
                &sVd[g][n][hh * 32 + tx * 4]);
            ulonglong2 vd1 = *reinterpret_cast<const ulonglong2*>(
                &sVd[g][n][hh * 32 + tx * 4 + 2]);
            ull wd = swd[hb0 + hc + hh];
            rabs(acc[0][0], u2.x, vd0.x, wd); rabs(acc[0][1], u2.y, vd0.x, wd);
            rabs(acc[1][0], u2.x, vd0.y, wd); rabs(acc[1][1], u2.y, vd0.y, wd);
            rabs(acc[2][0], u2.x, vd1.x, wd); rabs(acc[2][1], u2.y, vd1.x, wd);
            rabs(acc[3][0], u2.x, vd1.y, wd); rabs(acc[3][1], u2.y, vd1.y, wd);
        }
    }

    // write partial dots for this (g, n) quarter
#pragma unroll
    for (int q = 0; q < 4; q++) {
        int jl = tx * 4 + q;
        float2 x0 = unpk2(acc[q][0]);
        float2 x1 = unpk2(acc[q][1]);
        sdot[g][n][(ty * 4 + 0) * 32 + jl] = x0.x;
        sdot[g][n][(ty * 4 + 1) * 32 + jl] = x0.y;
        sdot[g][n][(ty * 4 + 2) * 32 + jl] = x1.x;
        sdot[g][n][(ty * 4 + 3) * 32 + jl] = x1.y;
    }
    __syncthreads();

    // combine halves + sigmoid + MSE: 4 cells per thread
    float b2 = b2v[0];
    float4 tA = *reinterpret_cast<const float4*>(&sdot[0][0][tid * 4]);
    float4 tB = *reinterpret_cast<const float4*>(&sdot[1][0][tid * 4]);
    float4 sA = *reinterpret_cast<const float4*>(&sdot[0][1][tid * 4]);
    float4 sB = *reinterpret_cast<const float4*>(&sdot[1][1][tid * 4]);
    float tv[4] = {tA.x + tB.x, tA.y + tB.y, tA.z + tB.z, tA.w + tB.w};
    float sv[4] = {sA.x + sB.x, sA.y + sB.y, sA.z + sB.z, sA.w + sB.w};
    int il = tid >> 3;
    int jl0 = (tid & 7) * 4;
    float local = 0.0f;
#pragma unroll
    for (int k = 0; k < 4; k++) {
        if (ib + il == jb + jl0 + k) continue;   // diagonal: rel == 0 in both
        float rt = 1.0f / (1.0f + __expf(-(tv[k] + b2)));
        float rs = 1.0f / (1.0f + __expf(-(sv[k] + b2)));
        float d = rs - rt;
        local = fmaf(d, d, local);
    }
    sred[tid] = local;
    __syncthreads();
    for (int st = 128; st > 0; st >>= 1) {
        if (tid < st) sred[tid] += sred[tid + st];
        __syncthreads();
    }
    if (tid == 0)
        atomicAdd(out, sred[0] * (1.0f / ((float)BN * (float)BN)));
}

// ---------------------------------------------------------------------------
extern "C" void kernel_launch(void* const* d_in, const int* in_sizes, int n_in,
                              void* d_out, int out_size) {
    const float* teacher = (const float*)d_in[0];
    const float* student = (const float*)d_in[1];
    const float* Wt = (const float*)d_in[2];
    const float* bt = (const float*)d_in[3];
    const float* Wsw = (const float*)d_in[4];
    const float* bs = (const float*)d_in[5];
    const float* W1 = (const float*)d_in[6];
    const float* b1 = (const float*)d_in[7];
    const float* W2 = (const float*)d_in[8];
    const float* b2 = (const float*)d_in[9];
    float* out = (float*)d_out;

    proj_gemm<<<dim3(16, 32, 2), 128>>>(teacher, Wt, student, Wsw, out, out_size);
    fused_sumuv<<<dim3(32, 2), 256>>>(bt, bs, W1, b1);
    pairwise_mse<<<dim3(16, 16), 256>>>(W2, b2, out);
}

// round 13
// speedup vs baseline: 1.1183x; 1.1183x over previous
#include <cuda_runtime.h>
#include <math.h>

#define BN 512
#define TD 2048
#define SD 768
#define HD 128

typedef unsigned long long ull;

// Scratch (device globals — no allocations allowed)
__device__ float g_tpp[32 * BN * HD];   // teacher proj partials (KLEN=64)
__device__ float g_spp[12 * BN * HD];   // student proj partials
__device__ float g_tp[BN * HD];
__device__ float g_sp[BN * HD];
// Transposed U/V: [h][row]
__device__ float g_UtT[HD * BN];
__device__ float g_VtT[HD * BN];
__device__ float g_UsT[HD * BN];
__device__ float g_VsT[HD * BN];
// Partial pre-sigmoid dots: [net*4 + hsplit][BN*BN]  (8 MB)
__device__ float g_pd[8][BN * BN];

// ---- packed f32x2 helpers (sm_100+) --------------------------------------
__device__ __forceinline__ ull pk2(float a, float b) {
    ull r; asm("mov.b64 %0, {%1, %2};" : "=l"(r) : "f"(a), "f"(b)); return r;
}
__device__ __forceinline__ float2 unpk2(ull v) {
    float2 r; asm("mov.b64 {%0, %1}, %2;" : "=f"(r.x), "=f"(r.y) : "l"(v)); return r;
}
__device__ __forceinline__ void fma2(ull &acc, ull a, ull b) {
    asm("fma.rn.f32x2 %0, %1, %2, %0;" : "+l"(acc) : "l"(a), "l"(b));
}
// acc += relu(u + v) * w, fully packed.
// relu(x)*w = (x + |x|) * (w/2); wh pre-halved. Exact vs fl(relu(x)*w).
__device__ __forceinline__ void rabs(ull &acc, ull u, ull v, ull wh) {
    asm("{\n\t"
        ".reg .b64 t, ta;\n\t"
        "add.rn.f32x2 t, %1, %2;\n\t"
        "and.b64 ta, t, 0x7FFFFFFF7FFFFFFF;\n\t"
        "add.rn.f32x2 t, t, ta;\n\t"
        "fma.rn.f32x2 %0, t, %3, %0;\n\t"
        "}"
        : "+l"(acc) : "l"(u), "l"(v), "l"(wh));
}

// ---------------------------------------------------------------------------
// Projection GEMM partials. z=0 teacher (32 k-splits), z=1 student (12).
// KLEN=64, KC=32 (2 chunks). Block: 32 rows x 128 cols, 128 thr, 4r x 8c.
// __launch_bounds__(128, 6) caps regs at ~85 -> 6 blocks/SM (24 warps).
// ---------------------------------------------------------------------------
__global__ void __launch_bounds__(128, 6)
proj_gemm(const float* __restrict__ T, const float* __restrict__ Wt,
          const float* __restrict__ S, const float* __restrict__ Ws) {
    const int KC = 32;
    const int XP = 36;
    __shared__ __align__(16) float Xst[KC * XP];      // [k][r] transposed
    __shared__ __align__(16) float Wsm[KC * HD];      // [kk][c]

    int z = blockIdx.z;
    int ky = blockIdx.y;
    const float* X; const float* W; float* outp; int ldx;
    if (z == 0) { X = T; W = Wt; ldx = TD; outp = g_tpp + ky * (BN * HD); }
    else {
        if (ky >= 12) return;
        X = S; W = Ws; ldx = SD; outp = g_spp + ky * (BN * HD);
    }

    int tid = threadIdx.x;        // 128
    int tx = tid & 15;            // cols tx*8..+7
    int ty = tid >> 4;            // rows ty*4..+3
    int row0 = blockIdx.x * 32;
    int k0 = ky * 64;

    ull acc[4][4];                // [colpair q][row m]
#pragma unroll
    for (int q = 0; q < 4; q++)
#pragma unroll
        for (int m = 0; m < 4; m++) acc[q][m] = 0ull;

#pragma unroll
    for (int kc = 0; kc < 64; kc += KC) {
#pragma unroll
        for (int t = 0; t < 2; t++) {
            int i4 = tid + t * 128;
            int r = i4 >> 3, k4 = (i4 & 7) * 4;
            float4 v = *reinterpret_cast<const float4*>(
                &X[(row0 + r) * ldx + k0 + kc + k4]);
            Xst[(k4 + 0) * XP + r] = v.x;
            Xst[(k4 + 1) * XP + r] = v.y;
            Xst[(k4 + 2) * XP + r] = v.z;
            Xst[(k4 + 3) * XP + r] = v.w;
        }
#pragma unroll
        for (int t = 0; t < 8; t++) {
            int i4 = tid + t * 128;
            int kk = i4 >> 5, c4 = (i4 & 31) * 4;
            float4 v = *reinterpret_cast<const float4*>(
                &W[(k0 + kc + kk) * HD + c4]);
            *reinterpret_cast<float4*>(&Wsm[kk * HD + c4]) = v;
        }
        __syncthreads();
#pragma unroll 8
        for (int kk = 0; kk < KC; kk++) {
            float4 a4 = *reinterpret_cast<const float4*>(&Xst[kk * XP + ty * 4]);
            ulonglong2 b01 = *reinterpret_cast<const ulonglong2*>(&Wsm[kk * HD + tx * 8]);
            ulonglong2 b23 = *reinterpret_cast<const ulonglong2*>(&Wsm[kk * HD + tx * 8 + 4]);
            ull a0 = pk2(a4.x, a4.x), a1 = pk2(a4.y, a4.y);
            ull a2 = pk2(a4.z, a4.z), a3 = pk2(a4.w, a4.w);
            fma2(acc[0][0], a0, b01.x); fma2(acc[0][1], a1, b01.x);
            fma2(acc[0][2], a2, b01.x); fma2(acc[0][3], a3, b01.x);
            fma2(acc[1][0], a0, b01.y); fma2(acc[1][1], a1, b01.y);
            fma2(acc[1][2], a2, b01.y); fma2(acc[1][3], a3, b01.y);
            fma2(acc[2][0], a0, b23.x); fma2(acc[2][1], a1, b23.x);
            fma2(acc[2][2], a2, b23.x); fma2(acc[2][3], a3, b23.x);
            fma2(acc[3][0], a0, b23.y); fma2(acc[3][1], a1, b23.y);
            fma2(acc[3][2], a2, b23.y); fma2(acc[3][3], a3, b23.y);
        }
        __syncthreads();
    }
#pragma unroll
    for (int m = 0; m < 4; m++) {
        int row = row0 + ty * 4 + m;
        float2 q0 = unpk2(acc[0][m]);
        float2 q1 = unpk2(acc[1][m]);
        float2 q2 = unpk2(acc[2][m]);
        float2 q3 = unpk2(acc[3][m]);
        *reinterpret_cast<float4*>(&outp[row * HD + tx * 8]) =
            make_float4(q0.x, q0.y, q1.x, q1.y);
        *reinterpret_cast<float4*>(&outp[row * HD + tx * 8 + 4]) =
            make_float4(q2.x, q2.y, q3.x, q3.y);
    }
}

// ---------------------------------------------------------------------------
// Sum proj partials + bias -> g_tp / g_sp. Grid 128 x 256 thr.
// Also zeroes the output scalar (block 0).
// ---------------------------------------------------------------------------
__global__ void __launch_bounds__(256)
sumtp(const float* __restrict__ bt, const float* __restrict__ bs,
      float* __restrict__ out, int out_size) {
    if (blockIdx.x == 0) {
        for (int i = threadIdx.x; i < out_size; i += 256) out[i] = 0.0f;
    }
    int b = blockIdx.x;
    int teacher = (b < 64);
    int i4 = (teacher ? b : b - 64) * 256 + threadIdx.x;
    int k4 = (i4 & 31) * 4;
    const float* bias = teacher ? bt : bs;
    const float* pbase = teacher ? g_tpp : g_spp;
    int np = teacher ? 32 : 12;

    float4 a0 = *reinterpret_cast<const float4*>(&bias[k4]);
    float4 a1 = make_float4(0.f, 0.f, 0.f, 0.f);
    float4 a2 = make_float4(0.f, 0.f, 0.f, 0.f);
    float4 a3 = make_float4(0.f, 0.f, 0.f, 0.f);
    for (int p = 0; p < np; p += 4) {
        float4 v0 = *reinterpret_cast<const float4*>(&pbase[(p + 0) * (BN * HD) + i4 * 4]);
        float4 v1 = *reinterpret_cast<const float4*>(&pbase[(p + 1) * (BN * HD) + i4 * 4]);
        float4 v2 = *reinterpret_cast<const float4*>(&pbase[(p + 2) * (BN * HD) + i4 * 4]);
        float4 v3 = *reinterpret_cast<const float4*>(&pbase[(p + 3) * (BN * HD) + i4 * 4]);
        a0.x += v0.x; a0.y += v0.y; a0.z += v0.z; a0.w += v0.w;
        a1.x += v1.x; a1.y += v1.y; a1.z += v1.z; a1.w += v1.w;
        a2.x += v2.x; a2.y += v2.y; a2.z += v2.z; a2.w += v2.w;
        a3.x += v3.x; a3.y += v3.y; a3.z += v3.z; a3.w += v3.w;
    }
    float4 r = make_float4(a0.x + a1.x + a2.x + a3.x,
                           a0.y + a1.y + a2.y + a3.y,
                           a0.z + a1.z + a2.z + a3.z,
                           a0.w + a1.w + a2.w + a3.w);
    float* dst = teacher ? g_tp : g_sp;
    *reinterpret_cast<float4*>(&dst[i4 * 4]) = r;
}

// ---------------------------------------------------------------------------
// U/V projections -> TRANSPOSED outputs [h][row].
// grid (16 rowblocks of 32, 4 mats), 256 thr. Micro 4r x 4c, acc packed
// over row pairs. (Champion R4 kernel, verbatim.)
// ---------------------------------------------------------------------------
__global__ void __launch_bounds__(256)
uv_gemm(const float* __restrict__ W1, const float* __restrict__ b1) {
    const int XP = 36;   // Xst stride [k][r]
    const int WP = 132;  // Wsm stride [kk][c]
    __shared__ __align__(16) float Xst[HD * XP];
    __shared__ __align__(16) float Wsm[32 * WP];

    int which = blockIdx.y;
    const float* X = (which < 2) ? g_tp : g_sp;
    const float* W = W1 + ((which & 1) ? HD * HD : 0);
    float* outT = (which == 0) ? g_UtT : (which == 1) ? g_VtT
                : (which == 2) ? g_UsT : g_VsT;
    bool add_bias = ((which & 1) == 0);

    int tid = threadIdx.x;       // 256
    int rowsel = tid & 7;        // rows rowsel*4..+3
    int colsel = tid >> 3;       // cols colsel*4..+3
    int r0 = blockIdx.x * 32;

    // stage X transposed [k][r]: 32 rows x 128 K (1024 float4, 4/thread)
#pragma unroll
    for (int t = 0; t < 4; t++) {
        int i4 = tid + t * 256;
        int r = i4 >> 5, k4 = (i4 & 31) * 4;
        float4 v = *reinterpret_cast<const float4*>(&X[(r0 + r) * HD + k4]);
        Xst[(k4 + 0) * XP + r] = v.x;
        Xst[(k4 + 1) * XP + r] = v.y;
        Xst[(k4 + 2) * XP + r] = v.z;
        Xst[(k4 + 3) * XP + r] = v.w;
    }

    ull acc[4][2];   // [col][rowpair]
#pragma unroll
    for (int c = 0; c < 4; c++) { acc[c][0] = 0ull; acc[c][1] = 0ull; }

    for (int kc = 0; kc < HD; kc += 32) {
        __syncthreads();
        // stage W chunk 32 x 128 (1024 float4, 4/thread)
#pragma unroll
        for (int t = 0; t < 4; t++) {
            int i4 = tid + t * 256;
            int kk = i4 >> 5, c4 = (i4 & 31) * 4;
            float4 v = *reinterpret_cast<const float4*>(&W[(kc + kk) * HD + c4]);
            *reinterpret_cast<float4*>(&Wsm[kk * WP + c4]) = v;
        }
        __syncthreads();
#pragma unroll 8
        for (int kk = 0; kk < 32; kk++) {
            int k = kc + kk;
            float2 a01 = *reinterpret_cast<const float2*>(&Xst[k * XP + rowsel * 4]);
            float2 a23 = *reinterpret_cast<const float2*>(&Xst[k * XP + rowsel * 4 + 2]);
            float4 w4 = *reinterpret_cast<const float4*>(&Wsm[kk * WP + colsel * 4]);
            ull ap0 = pk2(a01.x, a01.y), ap1 = pk2(a23.x, a23.y);
            ull w0 = pk2(w4.x, w4.x), w1 = pk2(w4.y, w4.y);
            ull w2d = pk2(w4.z, w4.z), w3 = pk2(w4.w, w4.w);
            fma2(acc[0][0], ap0, w0); fma2(acc[0][1], ap1, w0);
            fma2(acc[1][0], ap0, w1); fma2(acc[1][1], ap1, w1);
            fma2(acc[2][0], ap0, w2d); fma2(acc[2][1], ap1, w2d);
            fma2(acc[3][0], ap0, w3); fma2(acc[3][1], ap1, w3);
        }
    }

    // store transposed: for each col, float4 over 4 consecutive rows
#pragma unroll
    for (int c = 0; c < 4; c++) {
        int col = colsel * 4 + c;
        float bias = add_bias ? b1[col] : 0.0f;
        float2 v0 = unpk2(acc[c][0]);
        float2 v1 = unpk2(acc[c][1]);
        float4 r = make_float4(v0.x + bias, v0.y + bias,
                               v1.x + bias, v1.y + bias);
        *reinterpret_cast<float4*>(&outT[col * BN + r0 + rowsel * 4]) = r;
    }
}

// ---------------------------------------------------------------------------
// Pairwise partial dots. zz = net*4 + hsplit (HC=32). Tile 32(i) x 64(j),
// grid (8, 16, 8) = 1024 blocks, 128 thr, micro 4i x 4j, rabs + dup-packed V.
// ---------------------------------------------------------------------------
__global__ void __launch_bounds__(128)
pairwise_part(const float* __restrict__ w2) {
    const int HC = 32;
    __shared__ __align__(16) float sU[HC * 32];   // [h][i-row]
    __shared__ __align__(16) ull sVd[HC * 64];    // [h][j] dup-packed
    __shared__ ull swd[HC];

    int zz = blockIdx.z;
    int net = zz >> 2;
    int hc = (zz & 3) * HC;
    const float* UT = net ? g_UsT : g_UtT;
    const float* VT = net ? g_VsT : g_VtT;
    float* pd = g_pd[zz];

    int tid = threadIdx.x;       // 128
    int tx = tid & 15;           // j = jb + tx*4 + {0..3}
    int ty = tid >> 4;           // i = ib + ty*4 + {0..3}
    int jb = blockIdx.x * 64;
    int ib = blockIdx.y * 32;

    // stage U: 32h x 32r (256 f4, 2/thread)
#pragma unroll
    for (int t = 0; t < 2; t++) {
        int id = tid + t * 128;
        int h = id >> 3, r4 = (id & 7) * 4;
        *reinterpret_cast<float4*>(&sU[h * 32 + r4]) =
            *reinterpret_cast<const float4*>(&UT[(hc + h) * BN + ib + r4]);
    }
    // stage V dup-packed: 32h x 64j (4 f4/thread -> 8 STS.128)
#pragma unroll
    for (int t = 0; t < 4; t++) {
        int id = tid + t * 128;
        int h = id >> 4, c4 = (id & 15) * 4;
        float4 v = *reinterpret_cast<const float4*>(&VT[(hc + h) * BN + jb + c4]);
        ulonglong2 p0, p1;
        p0.x = pk2(v.x, v.x); p0.y = pk2(v.y, v.y);
        p1.x = pk2(v.z, v.z); p1.y = pk2(v.w, v.w);
        *reinterpret_cast<ulonglong2*>(&sVd[h * 64 + c4]) = p0;
        *reinterpret_cast<ulonglong2*>(&sVd[h * 64 + c4 + 2]) = p1;
    }
    if (tid < HC) { float w = w2[hc + tid] * 0.5f; swd[tid] = pk2(w, w); }
    __syncthreads();

    ull acc[4][2];               // [j-offset n][i-pair p]
#pragma unroll
    for (int n = 0; n < 4; n++) { acc[n][0] = 0ull; acc[n][1] = 0ull; }

#pragma unroll 8
    for (int hh = 0; hh < HC; hh++) {
        ulonglong2 u2 = *reinterpret_cast<const ulonglong2*>(&sU[hh * 32 + ty * 4]);
        ulonglong2 vd0 = *reinterpret_cast<const ulonglong2*>(&sVd[hh * 64 + tx * 4]);
        ulonglong2 vd1 = *reinterpret_cast<const ulonglong2*>(&sVd[hh * 64 + tx * 4 + 2]);
        ull wd = swd[hh];
        rabs(acc[0][0], u2.x, vd0.x, wd); rabs(acc[0][1], u2.y, vd0.x, wd);
        rabs(acc[1][0], u2.x, vd0.y, wd); rabs(acc[1][1], u2.y, vd0.y, wd);
        rabs(acc[2][0], u2.x, vd1.x, wd); rabs(acc[2][1], u2.y, vd1.x, wd);
        rabs(acc[3][0], u2.x, vd1.y, wd); rabs(acc[3][1], u2.y, vd1.y, wd);
    }

    float sums[4][4];            // [m][n]
#pragma unroll
    for (int n = 0; n < 4; n++) {
#pragma unroll
        for (int p = 0; p < 2; p++) {
            float2 v = unpk2(acc[n][p]);
            sums[p * 2 + 0][n] = v.x;
            sums[p * 2 + 1][n] = v.y;
        }
    }
#pragma unroll
    for (int m = 0; m < 4; m++) {
        int i = ib + ty * 4 + m;
        *reinterpret_cast<float4*>(&pd[i * BN + jb + tx * 4]) =
            make_float4(sums[m][0], sums[m][1], sums[m][2], sums[m][3]);
    }
}

// ---------------------------------------------------------------------------
// Reduce: rel = sigmoid(sum of 4 h-partials + b2) per net, diag skipped,
// MSE atomically accumulated into out. Loads front-batched for MLP=8.
// ---------------------------------------------------------------------------
__global__ void __launch_bounds__(256)
reduce_kernel(const float* __restrict__ b2v, float* __restrict__ out) {
    __shared__ float sred[256];
    int g = blockIdx.x * 256 + threadIdx.x;     // 65536 groups of 4
    int i = g >> 7;
    int j0 = (g & 127) * 4;
    float b2 = b2v[0];

    float4 t0 = *reinterpret_cast<const float4*>(&g_pd[0][g * 4]);
    float4 t1 = *reinterpret_cast<const float4*>(&g_pd[1][g * 4]);
    float4 t2 = *reinterpret_cast<const float4*>(&g_pd[2][g * 4]);
    float4 t3 = *reinterpret_cast<const float4*>(&g_pd[3][g * 4]);
    float4 s0 = *reinterpret_cast<const float4*>(&g_pd[4][g * 4]);
    float4 s1 = *reinterpret_cast<const float4*>(&g_pd[5][g * 4]);
    float4 s2 = *reinterpret_cast<const float4*>(&g_pd[6][g * 4]);
    float4 s3 = *reinterpret_cast<const float4*>(&g_pd[7][g * 4]);

    float tv[4] = {(t0.x + t1.x) + (t2.x + t3.x),
                   (t0.y + t1.y) + (t2.y + t3.y),
                   (t0.z + t1.z) + (t2.z + t3.z),
                   (t0.w + t1.w) + (t2.w + t3.w)};
    float sv[4] = {(s0.x + s1.x) + (s2.x + s3.x),
                   (s0.y + s1.y) + (s2.y + s3.y),
                   (s0.z + s1.z) + (s2.z + s3.z),
                   (s0.w + s1.w) + (s2.w + s3.w)};
    float local = 0.0f;
#pragma unroll
    for (int n = 0; n < 4; n++) {
        if (i == j0 + n) continue;   // diagonal: rel defined 0 in both
        float rt = 1.0f / (1.0f + __expf(-(tv[n] + b2)));
        float rs = 1.0f / (1.0f + __expf(-(sv[n] + b2)));
        float d = rs - rt;
        local = fmaf(d, d, local);
    }

    sred[threadIdx.x] = local;
    __syncthreads();
    for (int st = 128; st > 0; st >>= 1) {
        if (threadIdx.x < st) sred[threadIdx.x] += sred[threadIdx.x + st];
        __syncthreads();
    }
    if (threadIdx.x == 0)
        atomicAdd(out, sred[0] * (1.0f / ((float)BN * (float)BN)));
}

// ---------------------------------------------------------------------------
extern "C" void kernel_launch(void* const* d_in, const int* in_sizes, int n_in,
                              void* d_out, int out_size) {
    const float* teacher = (const float*)d_in[0];
    const float* student = (const float*)d_in[1];
    const float* Wt = (const float*)d_in[2];
    const float* bt = (const float*)d_in[3];
    const float* Wsw = (const float*)d_in[4];
    const float* bs = (const float*)d_in[5];
    const float* W1 = (const float*)d_in[6];
    const float* b1 = (const float*)d_in[7];
    const float* W2 = (const float*)d_in[8];
    const float* b2 = (const float*)d_in[9];
    float* out = (float*)d_out;

    proj_gemm<<<dim3(16, 32, 2), 128>>>(teacher, Wt, student, Wsw);
    sumtp<<<128, 256>>>(bt, bs, out, out_size);
    uv_gemm<<<dim3(16, 4), 256>>>(W1, b1);
    pairwise_part<<<dim3(8, 16, 8), 128>>>(W2);
    reduce_kernel<<<256, 256>>>(b2, out);
}